// round 1
// baseline (speedup 1.0000x reference)
#include <cuda_runtime.h>

#define BATCH   128
#define LSIG    128000
#define NFFT    1024
#define HOP     320
#define NMELS   128
#define NFRAMES 401
#define NFREQ   513            // NFFT/2 + 1
#define MAXW    40             // max freq bins per mel triangle (~27 actual)
#define PI_D    3.14159265358979323846

// ---------------- device globals (scratch; no allocations allowed) ----------
__device__ float  g_win[NFFT];
__device__ float2 g_tw[NFFT / 2];
__device__ int    g_mlo[NMELS];
__device__ int    g_mlen[NMELS];
__device__ float  g_fbw[MAXW][NMELS];                  // transposed: coalesced by m
__device__ float  g_mel[BATCH * NFRAMES * NMELS];      // [b][t][m]
__device__ float  g_stats[BATCH][2];                   // mean, 1/(std+1e-6)

// ---------------- init: window, twiddles, compact mel filterbank ------------
__global__ void init_kernel() {
    int tid = threadIdx.x;

    if (tid < NFFT) {
        double w = 0.5 * (1.0 - cos(2.0 * PI_D * (double)tid / (double)NFFT));
        g_win[tid] = (float)w;
    }
    if (tid < NFFT / 2) {
        double ang = -2.0 * PI_D * (double)tid / (double)NFFT;
        g_tw[tid] = make_float2((float)cos(ang), (float)sin(ang));
    }
    if (tid < NMELS) {
        int m = tid;
        // HTK mel points (matches torchaudio melscale_fbanks defaults)
        double mel_max = 2595.0 * log10(1.0 + 16000.0 / 700.0);
        double f0 = 700.0 * (pow(10.0, (mel_max * (double)(m    ) / 129.0) / 2595.0) - 1.0);
        double f1 = 700.0 * (pow(10.0, (mel_max * (double)(m + 1) / 129.0) / 2595.0) - 1.0);
        double f2 = 700.0 * (pow(10.0, (mel_max * (double)(m + 2) / 129.0) / 2595.0) - 1.0);

        const double df = 16000.0 / 512.0;   // 31.25 Hz per bin
        int lo = -1, hi = -1;
        for (int f = 0; f < NFREQ; f++) {
            double freq = f * df;
            double down = (freq - f0) / (f1 - f0);
            double up   = (f2 - freq) / (f2 - f1);
            double w    = fmin(down, up);
            if (w > 0.0) { if (lo < 0) lo = f; hi = f; }
        }
        if (lo < 0) {
            g_mlo[m] = 0; g_mlen[m] = 0;
        } else {
            int len = hi - lo + 1;
            if (len > MAXW) len = MAXW;     // safety clamp (never hit: max ~27)
            g_mlo[m] = lo; g_mlen[m] = len;
            for (int i = 0; i < len; i++) {
                double freq = (double)(lo + i) * df;
                double down = (freq - f0) / (f1 - f0);
                double up   = (f2 - freq) / (f2 - f1);
                double w    = fmin(down, up);
                if (w < 0.0) w = 0.0;
                g_fbw[i][m] = (float)w;
            }
        }
    }
}

// ---------------- mel spectrogram: 1 CTA per (b, t) frame -------------------
// 256 threads: reflect-pad load + window, Stockham radix-2 1024-pt complex
// FFT (self-sorting) in shared, |X| for 513 bins, sparse mel gather.
__global__ __launch_bounds__(256) void melspec_kernel(const float* __restrict__ x) {
    const int t = blockIdx.x;   // frame 0..400
    const int b = blockIdx.y;   // batch 0..127
    const int tid = threadIdx.x;

    __shared__ float2 bufA[NFFT];
    __shared__ float2 bufB[NFFT];
    __shared__ float2 tws[NFFT / 2];

    // stage twiddles into shared (read 10x per point otherwise)
    #pragma unroll
    for (int i = tid; i < NFFT / 2; i += 256) tws[i] = g_tw[i];

    // load frame with reflect padding (pad = 512), apply window
    const float* __restrict__ xb = x + (long long)b * LSIG;
    const int base = t * HOP - NFFT / 2;
    #pragma unroll
    for (int r = 0; r < 4; r++) {
        int j = tid + r * 256;
        int p = base + j;
        if (p < 0) p = -p;
        if (p >= LSIG) p = 2 * LSIG - 2 - p;
        bufA[j] = make_float2(xb[p] * g_win[j], 0.0f);
    }
    __syncthreads();

    // Stockham radix-2, 10 stages, ping-pong A<->B, result back in A
    float2* src = bufA;
    float2* dst = bufB;
    int s = 1;
    #pragma unroll
    for (int stage = 0; stage < 10; stage++) {
        #pragma unroll
        for (int r = 0; r < 2; r++) {
            int tt = tid + r * 256;           // butterfly id 0..511
            int q  = tt & (s - 1);
            float2 a = src[tt];
            float2 c = src[tt + NFFT / 2];
            float2 w = tws[tt & ~(s - 1)];    // tw[p*s], p = tt>>stage
            float2 sum = make_float2(a.x + c.x, a.y + c.y);
            float2 dif = make_float2(a.x - c.x, a.y - c.y);
            float2 pr  = make_float2(dif.x * w.x - dif.y * w.y,
                                     dif.x * w.y + dif.y * w.x);
            int di = 2 * tt - q;              // q + 2*s*p
            dst[di]     = sum;
            dst[di + s] = pr;
        }
        __syncthreads();
        float2* tmp = src; src = dst; dst = tmp;
        s <<= 1;
    }

    // magnitudes of bins 0..512 into shared (reuse the free buffer)
    float* smag = (float*)dst;                // dst == bufB after 10 swaps
    for (int f = tid; f < NFREQ; f += 256) {
        float2 v = src[f];
        smag[f] = sqrtf(v.x * v.x + v.y * v.y);
    }
    __syncthreads();

    // deterministic mel gather: thread m sums its triangle
    if (tid < NMELS) {
        int lo  = g_mlo[tid];
        int len = g_mlen[tid];
        float acc = 0.0f;
        for (int i = 0; i < len; i++)
            acc += smag[lo + i] * g_fbw[i][tid];
        g_mel[((long long)b * NFRAMES + t) * NMELS + tid] = acc;
    }
}

// ---------------- PCEN IIR + power law + per-batch stats --------------------
__global__ __launch_bounds__(NMELS) void pcen_kernel(float* __restrict__ out) {
    const int b = blockIdx.x;
    const int m = threadIdx.x;

    const float* __restrict__ mel = g_mel + (long long)b * NFRAMES * NMELS;
    float* __restrict__ ob = out + ((long long)b * NMELS + m) * NFRAMES;

    const float s1 = 0.975f;       // 1 - PCEN_S
    const float s0 = 0.025f;       // PCEN_S
    const float sqrt2 = 1.41421356237309515f;

    float M = 0.0f;
    double sum = 0.0, sumsq = 0.0;

    for (int t = 0; t < NFRAMES; t++) {
        float xv = mel[t * NMELS + m];
        M = (t == 0) ? xv : (s1 * M + s0 * xv);
        float smooth = powf(1e-6f + M, 0.98f);
        float p = sqrtf(xv / smooth + 2.0f) - sqrt2;
        ob[t] = p;
        sum   += (double)p;
        sumsq += (double)p * (double)p;
    }

    __shared__ double ssum[NMELS];
    __shared__ double ssq[NMELS];
    ssum[m] = sum; ssq[m] = sumsq;
    __syncthreads();
    for (int o = NMELS / 2; o > 0; o >>= 1) {
        if (m < o) { ssum[m] += ssum[m + o]; ssq[m] += ssq[m + o]; }
        __syncthreads();
    }
    if (m == 0) {
        const double n = (double)(NMELS * NFRAMES);
        double mean = ssum[0] / n;
        double var  = (ssq[0] - ssum[0] * ssum[0] / n) / (n - 1.0);
        if (var < 0.0) var = 0.0;
        g_stats[b][0] = (float)mean;
        g_stats[b][1] = (float)(1.0 / (sqrt(var) + 1e-6));
    }
}

// ---------------- in-place standardization ----------------------------------
__global__ void norm_kernel(float* __restrict__ out, int total) {
    int i = blockIdx.x * blockDim.x + threadIdx.x;
    if (i >= total) return;
    int b = i / (NMELS * NFRAMES);
    out[i] = (out[i] - g_stats[b][0]) * g_stats[b][1];
}

// ---------------- launch ------------------------------------------------------
extern "C" void kernel_launch(void* const* d_in, const int* in_sizes, int n_in,
                              void* d_out, int out_size) {
    const float* x = (const float*)d_in[0];
    float* out = (float*)d_out;

    init_kernel<<<1, 1024>>>();
    melspec_kernel<<<dim3(NFRAMES, BATCH), 256>>>(x);
    pcen_kernel<<<BATCH, NMELS>>>(out);
    int total = BATCH * NMELS * NFRAMES;
    norm_kernel<<<(total + 255) / 256, 256>>>(out, total);
}

// round 2
// speedup vs baseline: 1.2933x; 1.2933x over previous
#include <cuda_runtime.h>

#define BATCH   128
#define LSIG    128000
#define NFFT    1024
#define HOP     320
#define NMELS   128
#define NFRAMES 401
#define NFREQ   513            // NFFT/2 + 1
#define MAXW    40             // max freq bins per mel triangle (~27 actual)
#define PI_D    3.14159265358979323846

// ---------------- device globals (scratch; no allocations allowed) ----------
__device__ float  g_win[NFFT];
__device__ float2 g_tw[NFFT / 2];                      // e^{-2*pi*i*k/1024}, k=0..511
__device__ int    g_mlo[NMELS];
__device__ int    g_mlen[NMELS];
__device__ float  g_fbw[MAXW][NMELS];                  // transposed: coalesced by m
__device__ float  g_mel[BATCH * NFRAMES * NMELS];      // [b][t][m]
__device__ float  g_stats[BATCH][2];                   // mean, 1/(std+1e-6)

// ---------------- init: window, twiddles, compact mel filterbank ------------
__global__ void init_kernel() {
    int tid = threadIdx.x;

    if (tid < NFFT) {
        double w = 0.5 * (1.0 - cos(2.0 * PI_D * (double)tid / (double)NFFT));
        g_win[tid] = (float)w;
    }
    if (tid < NFFT / 2) {
        double ang = -2.0 * PI_D * (double)tid / (double)NFFT;
        g_tw[tid] = make_float2((float)cos(ang), (float)sin(ang));
    }
    if (tid < NMELS) {
        int m = tid;
        // HTK mel points (matches torchaudio melscale_fbanks defaults)
        double mel_max = 2595.0 * log10(1.0 + 16000.0 / 700.0);
        double f0 = 700.0 * (pow(10.0, (mel_max * (double)(m    ) / 129.0) / 2595.0) - 1.0);
        double f1 = 700.0 * (pow(10.0, (mel_max * (double)(m + 1) / 129.0) / 2595.0) - 1.0);
        double f2 = 700.0 * (pow(10.0, (mel_max * (double)(m + 2) / 129.0) / 2595.0) - 1.0);

        const double df = 16000.0 / 512.0;   // 31.25 Hz per bin
        int lo = -1, hi = -1;
        for (int f = 0; f < NFREQ; f++) {
            double freq = f * df;
            double down = (freq - f0) / (f1 - f0);
            double up   = (f2 - freq) / (f2 - f1);
            double w    = fmin(down, up);
            if (w > 0.0) { if (lo < 0) lo = f; hi = f; }
        }
        if (lo < 0) {
            g_mlo[m] = 0; g_mlen[m] = 0;
        } else {
            int len = hi - lo + 1;
            if (len > MAXW) len = MAXW;     // safety clamp (never hit: max ~27)
            g_mlo[m] = lo; g_mlen[m] = len;
            for (int i = 0; i < len; i++) {
                double freq = (double)(lo + i) * df;
                double down = (freq - f0) / (f1 - f0);
                double up   = (f2 - freq) / (f2 - f1);
                double w    = fmin(down, up);
                if (w < 0.0) w = 0.0;
                g_fbw[i][m] = (float)w;
            }
        }
    }
}

// ---------------- mel spectrogram: 1 CTA per (b, t) frame -------------------
// Real-input packing: z[n] = x[2n]w[2n] + i*x[2n+1]w[2n+1] (512 complex pts),
// 9-stage Stockham radix-2 (1 butterfly/thread/stage), O(N) unpack to rfft
// magnitudes, then sparse mel gather. Shared traffic ~2.2x less than the
// naive 1024-pt complex FFT.
__global__ __launch_bounds__(256) void melspec_kernel(const float* __restrict__ x) {
    const int t = blockIdx.x;   // frame 0..400
    const int b = blockIdx.y;   // batch 0..127
    const int tid = threadIdx.x;

    __shared__ float2 bufA[512];
    __shared__ float2 bufB[512];
    __shared__ float2 tws[256];          // e^{-2*pi*i*k/512}

    tws[tid] = g_tw[2 * tid];

    // load 1024 windowed real samples packed into 512 complex (reflect pad 512)
    const float* __restrict__ xb = x + (long long)b * LSIG;
    const int base = t * HOP - NFFT / 2;
    #pragma unroll
    for (int r = 0; r < 2; r++) {
        int n  = tid + r * 256;          // complex index 0..511
        int p0 = base + 2 * n;
        int p1 = p0 + 1;
        if (p0 < 0) p0 = -p0;
        if (p0 >= LSIG) p0 = 2 * LSIG - 2 - p0;
        if (p1 < 0) p1 = -p1;
        if (p1 >= LSIG) p1 = 2 * LSIG - 2 - p1;
        bufA[n] = make_float2(xb[p0] * g_win[2 * n],
                              xb[p1] * g_win[2 * n + 1]);
    }
    __syncthreads();

    // Stockham radix-2, 9 stages over 512 points, 256 butterflies = 1/thread
    float2* src = bufA;
    float2* dst = bufB;
    int s = 1;
    #pragma unroll
    for (int stage = 0; stage < 9; stage++) {
        int tt = tid;
        int q  = tt & (s - 1);
        float2 a = src[tt];
        float2 c = src[tt + 256];
        float2 w = tws[tt & ~(s - 1)];
        float2 sum = make_float2(a.x + c.x, a.y + c.y);
        float2 dif = make_float2(a.x - c.x, a.y - c.y);
        float2 pr  = make_float2(dif.x * w.x - dif.y * w.y,
                                 dif.x * w.y + dif.y * w.x);
        int di = 2 * tt - q;
        dst[di]     = sum;
        dst[di + s] = pr;
        __syncthreads();
        float2* tmp = src; src = dst; dst = tmp;
        s <<= 1;
    }
    // after 9 swaps: data in src(=bufB), dst(=bufA) is free

    // unpack to rfft magnitudes: X[k] = E[k] + e^{-2*pi*i*k/1024} * O[k]
    float* smag = (float*)dst;           // 513 floats fit in bufA (1024 floats)
    #pragma unroll
    for (int r = 0; r < 2; r++) {
        int k = tid + r * 256;
        float2 Zk = src[k];
        float2 Zr = src[(512 - k) & 511];
        float ex = 0.5f * (Zk.x + Zr.x);
        float ey = 0.5f * (Zk.y - Zr.y);
        float ox = 0.5f * (Zk.y + Zr.y);            // O = (Z - conj(Zr)) * (-i)/2
        float oy = 0.5f * (Zr.x - Zk.x);
        float2 w = g_tw[k];                          // e^{-2*pi*i*k/1024}
        float xr = ex + ox * w.x - oy * w.y;
        float xi = ey + ox * w.y + oy * w.x;
        smag[k] = sqrtf(xr * xr + xi * xi);
    }
    if (tid == 0) {
        float2 Z0 = src[0];
        smag[512] = fabsf(Z0.x - Z0.y);              // Nyquist bin
    }
    __syncthreads();

    // deterministic mel gather: thread m sums its triangle
    if (tid < NMELS) {
        int lo  = g_mlo[tid];
        int len = g_mlen[tid];
        float acc = 0.0f;
        for (int i = 0; i < len; i++)
            acc += smag[lo + i] * g_fbw[i][tid];
        g_mel[((long long)b * NFRAMES + t) * NMELS + tid] = acc;
    }
}

// ---------------- PCEN IIR + power law + per-batch stats --------------------
__global__ __launch_bounds__(NMELS) void pcen_kernel(float* __restrict__ out) {
    const int b = blockIdx.x;
    const int m = threadIdx.x;

    const float* __restrict__ mel = g_mel + (long long)b * NFRAMES * NMELS;
    float* __restrict__ ob = out + ((long long)b * NMELS + m) * NFRAMES;

    const float s1 = 0.975f;       // 1 - PCEN_S
    const float s0 = 0.025f;       // PCEN_S
    const float sqrt2 = 1.41421356237309515f;

    float M = 0.0f;
    double sum = 0.0, sumsq = 0.0;

    float xnext = mel[m];          // software-pipelined load
    for (int t = 0; t < NFRAMES; t++) {
        float xv = xnext;
        if (t + 1 < NFRAMES) xnext = mel[(t + 1) * NMELS + m];
        M = (t == 0) ? xv : fmaf(s1, M, s0 * xv);
        float smooth = __powf(1e-6f + M, 0.98f);
        float p = sqrtf(xv / smooth + 2.0f) - sqrt2;
        ob[t] = p;
        sum   += (double)p;
        sumsq += (double)p * (double)p;
    }

    __shared__ double ssum[NMELS];
    __shared__ double ssq[NMELS];
    ssum[m] = sum; ssq[m] = sumsq;
    __syncthreads();
    for (int o = NMELS / 2; o > 0; o >>= 1) {
        if (m < o) { ssum[m] += ssum[m + o]; ssq[m] += ssq[m + o]; }
        __syncthreads();
    }
    if (m == 0) {
        const double n = (double)(NMELS * NFRAMES);
        double mean = ssum[0] / n;
        double var  = (ssq[0] - ssum[0] * ssum[0] / n) / (n - 1.0);
        if (var < 0.0) var = 0.0;
        g_stats[b][0] = (float)mean;
        g_stats[b][1] = (float)(1.0 / (sqrt(var) + 1e-6));
    }
}

// ---------------- in-place standardization ----------------------------------
__global__ void norm_kernel(float* __restrict__ out, int total) {
    int i = blockIdx.x * blockDim.x + threadIdx.x;
    if (i >= total) return;
    int b = i / (NMELS * NFRAMES);
    out[i] = (out[i] - g_stats[b][0]) * g_stats[b][1];
}

// ---------------- launch ------------------------------------------------------
extern "C" void kernel_launch(void* const* d_in, const int* in_sizes, int n_in,
                              void* d_out, int out_size) {
    const float* x = (const float*)d_in[0];
    float* out = (float*)d_out;

    init_kernel<<<1, 1024>>>();
    melspec_kernel<<<dim3(NFRAMES, BATCH), 256>>>(x);
    pcen_kernel<<<BATCH, NMELS>>>(out);
    int total = BATCH * NMELS * NFRAMES;
    norm_kernel<<<(total + 255) / 256, 256>>>(out, total);
}

// round 3
// speedup vs baseline: 1.4537x; 1.1240x over previous
#include <cuda_runtime.h>

#define BATCH   128
#define LSIG    128000
#define NFFT    1024
#define HOP     320
#define NMELS   128
#define NFRAMES 401
#define NFREQ   513
#define MAXW    40
#define PI_D    3.14159265358979323846

// ---------------- device globals (no allocations allowed) -------------------
__device__ float2 g_win2[512];                 // (w[2n], w[2n+1]) interleaved hann
__device__ float2 g_tw[512];                   // W_1024^k = e^{-2*pi*i*k/1024}
__device__ int    g_mlo[NMELS];
__device__ int    g_mlen[NMELS];
__device__ float  g_fbw[MAXW][NMELS];          // transposed: coalesced by m
__device__ float  g_mel[BATCH * NFRAMES * NMELS];
__device__ float  g_stats[BATCH][2];

// ---------------- complex helpers -------------------------------------------
__device__ __forceinline__ float2 cadd(float2 a, float2 b){return make_float2(a.x+b.x, a.y+b.y);}
__device__ __forceinline__ float2 csub(float2 a, float2 b){return make_float2(a.x-b.x, a.y-b.y);}
__device__ __forceinline__ float2 cmul(float2 a, float2 b){return make_float2(a.x*b.x - a.y*b.y, a.x*b.y + a.y*b.x);}

// W_512^m lookup from 256-entry table of W_512^{0..255} (sign trick for m>=256)
__device__ __forceinline__ float2 twl512(const float2* tws, int m) {
    float2 w = tws[m & 255];
    return (m & 256) ? make_float2(-w.x, -w.y) : w;
}

// in-place 8-point DFT (b_k = sum_j v_j W8^{jk}), ~52 flops, all registers
__device__ __forceinline__ void dft8(float2 v[8]) {
    const float C = 0.70710678118654752f;
    float2 s0 = cadd(v[0], v[4]), d0 = csub(v[0], v[4]);
    float2 s1 = cadd(v[2], v[6]), d1 = csub(v[2], v[6]);
    float2 s2 = cadd(v[1], v[5]), d2 = csub(v[1], v[5]);
    float2 s3 = cadd(v[3], v[7]), d3 = csub(v[3], v[7]);
    float2 e0 = cadd(s0, s1), e2 = csub(s0, s1);
    float2 nid1 = make_float2(d1.y, -d1.x);                 // -i * d1
    float2 e1 = cadd(d0, nid1), e3 = csub(d0, nid1);
    float2 o0 = cadd(s2, s3), o2 = csub(s2, s3);
    float2 nid3 = make_float2(d3.y, -d3.x);                 // -i * d3
    float2 o1 = cadd(d2, nid3), o3 = csub(d2, nid3);
    float2 t1 = make_float2(C*(o1.x + o1.y), C*(o1.y - o1.x));   // W8^1 * o1
    float2 t2 = make_float2(o2.y, -o2.x);                        // W8^2 * o2 = -i*o2
    float2 t3 = make_float2(C*(o3.y - o3.x), -C*(o3.x + o3.y));  // W8^3 * o3
    v[0] = cadd(e0, o0); v[4] = csub(e0, o0);
    v[1] = cadd(e1, t1); v[5] = csub(e1, t1);
    v[2] = cadd(e2, t2); v[6] = csub(e2, t2);
    v[3] = cadd(e3, t3); v[7] = csub(e3, t3);
}

#define PAD(i) ((i) + ((i) >> 3))   // 512 logical -> 576 physical, conflict-free stores

// ---------------- init: window, twiddles, compact mel filterbank ------------
__global__ void init_kernel() {
    int tid = threadIdx.x;

    if (tid < 512) {
        double w0 = 0.5 * (1.0 - cos(2.0 * PI_D * (double)(2*tid)     / (double)NFFT));
        double w1 = 0.5 * (1.0 - cos(2.0 * PI_D * (double)(2*tid + 1) / (double)NFFT));
        g_win2[tid] = make_float2((float)w0, (float)w1);
        double ang = -2.0 * PI_D * (double)tid / (double)NFFT;
        g_tw[tid] = make_float2((float)cos(ang), (float)sin(ang));
    }
    if (tid < NMELS) {
        int m = tid;
        double mel_max = 2595.0 * log10(1.0 + 16000.0 / 700.0);
        double f0 = 700.0 * (pow(10.0, (mel_max * (double)(m    ) / 129.0) / 2595.0) - 1.0);
        double f1 = 700.0 * (pow(10.0, (mel_max * (double)(m + 1) / 129.0) / 2595.0) - 1.0);
        double f2 = 700.0 * (pow(10.0, (mel_max * (double)(m + 2) / 129.0) / 2595.0) - 1.0);

        const double df = 16000.0 / 512.0;
        int lo = -1, hi = -1;
        for (int f = 0; f < NFREQ; f++) {
            double freq = f * df;
            double down = (freq - f0) / (f1 - f0);
            double up   = (f2 - freq) / (f2 - f1);
            double w    = fmin(down, up);
            if (w > 0.0) { if (lo < 0) lo = f; hi = f; }
        }
        if (lo < 0) { g_mlo[m] = 0; g_mlen[m] = 0; }
        else {
            int len = hi - lo + 1;
            if (len > MAXW) len = MAXW;
            g_mlo[m] = lo; g_mlen[m] = len;
            for (int i = 0; i < len; i++) {
                double freq = (double)(lo + i) * df;
                double down = (freq - f0) / (f1 - f0);
                double up   = (f2 - freq) / (f2 - f1);
                double w    = fmin(down, up);
                if (w < 0.0) w = 0.0;
                g_fbw[i][m] = (float)w;
            }
        }
    }
}

// ---------------- mel spectrogram: 4 frames per 256-thread CTA --------------
// Per frame: 64 threads, radix-8 register Stockham FFT over 512 packed complex
// points (real-input fold), 3 stages, 2 shared exchanges, O(N) rfft unpack,
// sparse mel gather. 6 syncthreads per frame-group total.
__global__ __launch_bounds__(256) void melspec_kernel(const float* __restrict__ x) {
    __shared__ float  sA[4][2][576];
    __shared__ float  sB[4][2][576];
    __shared__ float2 tws[256];                 // W_512^{0..255}

    const int tid = threadIdx.x;
    const int fl  = tid >> 6;                   // frame slot 0..3
    const int ft  = tid & 63;                   // thread within frame
    int t = blockIdx.x * 4 + fl;
    const bool valid = (t < NFRAMES);
    if (!valid) t = NFRAMES - 1;
    const int b = blockIdx.y;

    tws[tid & 255] = g_tw[2 * (tid & 255)];     // 256 threads cover all 256

    // load: z[n] = x[2n]w[2n] + i x[2n+1]w[2n+1], thread ft holds n = ft + 64j
    const float* __restrict__ xb = x + (long long)b * LSIG;
    const int base = t * HOP - 512;             // always even
    float2 v[8];
    if (base >= 0 && base + (NFFT - 1) < LSIG) {
        const float2* __restrict__ x2 = (const float2*)(xb + base);
        #pragma unroll
        for (int j = 0; j < 8; j++) {
            int n = ft + 64 * j;
            float2 s = x2[n];
            float2 w = g_win2[n];
            v[j] = make_float2(s.x * w.x, s.y * w.y);
        }
    } else {
        #pragma unroll
        for (int j = 0; j < 8; j++) {
            int n  = ft + 64 * j;
            int p0 = base + 2 * n, p1 = p0 + 1;
            p0 = p0 < 0 ? -p0 : (p0 >= LSIG ? 2 * LSIG - 2 - p0 : p0);
            p1 = p1 < 0 ? -p1 : (p1 >= LSIG ? 2 * LSIG - 2 - p1 : p1);
            float2 w = g_win2[n];
            v[j] = make_float2(xb[p0] * w.x, xb[p1] * w.y);
        }
    }
    __syncthreads();                            // tws visible

    // ---- stage 0: s=1, p=ft, q=0; out[8*ft + k] = DFT8_k * W512^{ft*k}
    dft8(v);
    #pragma unroll
    for (int k = 1; k < 8; k++) v[k] = cmul(v[k], twl512(tws, ft * k));
    #pragma unroll
    for (int k = 0; k < 8; k++) {
        int P = PAD(8 * ft + k);
        sA[fl][0][P] = v[k].x; sA[fl][1][P] = v[k].y;
    }
    __syncthreads();

    // ---- stage 1: s=8, p=ft>>3, q=ft&7; out[64p + q + 8k] = DFT8_k * W512^{8pk}
    #pragma unroll
    for (int j = 0; j < 8; j++) {
        int P = PAD(ft + 64 * j);
        v[j] = make_float2(sA[fl][0][P], sA[fl][1][P]);
    }
    dft8(v);
    {
        int p = ft >> 3, q = ft & 7;
        #pragma unroll
        for (int k = 1; k < 8; k++) v[k] = cmul(v[k], twl512(tws, 8 * p * k));
        #pragma unroll
        for (int k = 0; k < 8; k++) {
            int P = PAD(64 * p + q + 8 * k);
            sB[fl][0][P] = v[k].x; sB[fl][1][P] = v[k].y;
        }
    }
    __syncthreads();

    // ---- stage 2: s=64, p=0, q=ft; out[ft + 64k] = DFT8_k (no twiddle)
    #pragma unroll
    for (int j = 0; j < 8; j++) {
        int P = PAD(ft + 64 * j);
        v[j] = make_float2(sB[fl][0][P], sB[fl][1][P]);
    }
    dft8(v);
    #pragma unroll
    for (int k = 0; k < 8; k++) {
        int P = PAD(ft + 64 * k);
        sA[fl][0][P] = v[k].x; sA[fl][1][P] = v[k].y;
    }
    __syncthreads();

    // ---- unpack rfft magnitudes: X[k] = E[k] + W_1024^k * O[k]
    float* smag = sB[fl][0];                    // 576 >= 513, sB free now
    #pragma unroll
    for (int r = 0; r < 8; r++) {
        int k  = ft + 64 * r;
        int Pk = PAD(k), Pr = PAD((512 - k) & 511);
        float zkx = sA[fl][0][Pk], zky = sA[fl][1][Pk];
        float zrx = sA[fl][0][Pr], zry = sA[fl][1][Pr];
        float ex = 0.5f * (zkx + zrx), ey = 0.5f * (zky - zry);
        float ox = 0.5f * (zky + zry), oy = 0.5f * (zrx - zkx);
        float2 w = g_tw[k];
        float xr = ex + ox * w.x - oy * w.y;
        float xi = ey + ox * w.y + oy * w.x;
        smag[k] = sqrtf(xr * xr + xi * xi);
    }
    if (ft == 0)
        smag[512] = fabsf(sA[fl][0][PAD(0)] - sA[fl][1][PAD(0)]);   // Nyquist
    __syncthreads();

    // ---- mel gather: thread ft handles mels ft and ft+64
    if (valid) {
        float* __restrict__ om = g_mel + ((long long)b * NFRAMES + t) * NMELS;
        #pragma unroll
        for (int h = 0; h < 2; h++) {
            int m   = ft + 64 * h;
            int lo  = g_mlo[m];
            int len = g_mlen[m];
            float acc = 0.0f;
            for (int i = 0; i < len; i++)
                acc += smag[lo + i] * g_fbw[i][m];
            om[m] = acc;
        }
    }
}

// ---------------- PCEN IIR + power law + per-batch stats --------------------
__global__ __launch_bounds__(NMELS) void pcen_kernel(float* __restrict__ out) {
    const int b = blockIdx.x;
    const int m = threadIdx.x;

    const float* __restrict__ mel = g_mel + (long long)b * NFRAMES * NMELS;
    float* __restrict__ ob = out + ((long long)b * NMELS + m) * NFRAMES;

    const float s1 = 0.975f, s0 = 0.025f;
    const float sqrt2 = 1.41421356237309515f;

    float M = 0.0f;
    double sum = 0.0, sumsq = 0.0;

    float xnext = mel[m];
    for (int t = 0; t < NFRAMES; t++) {
        float xv = xnext;
        if (t + 1 < NFRAMES) xnext = mel[(t + 1) * NMELS + m];
        M = (t == 0) ? xv : fmaf(s1, M, s0 * xv);
        float smooth = __powf(1e-6f + M, 0.98f);
        float p = sqrtf(xv / smooth + 2.0f) - sqrt2;
        ob[t] = p;
        sum   += (double)p;
        sumsq += (double)p * (double)p;
    }

    __shared__ double ssum[NMELS];
    __shared__ double ssq[NMELS];
    ssum[m] = sum; ssq[m] = sumsq;
    __syncthreads();
    for (int o = NMELS / 2; o > 0; o >>= 1) {
        if (m < o) { ssum[m] += ssum[m + o]; ssq[m] += ssq[m + o]; }
        __syncthreads();
    }
    if (m == 0) {
        const double n = (double)(NMELS * NFRAMES);
        double mean = ssum[0] / n;
        double var  = (ssq[0] - ssum[0] * ssum[0] / n) / (n - 1.0);
        if (var < 0.0) var = 0.0;
        g_stats[b][0] = (float)mean;
        g_stats[b][1] = (float)(1.0 / (sqrt(var) + 1e-6));
    }
}

// ---------------- in-place standardization (vectorized) ---------------------
__global__ void norm_kernel(float4* __restrict__ out, int total4) {
    int i = blockIdx.x * blockDim.x + threadIdx.x;
    if (i >= total4) return;
    int b = (i * 4) / (NMELS * NFRAMES);        // 51328 % 4 == 0: no straddle
    float mean = g_stats[b][0], inv = g_stats[b][1];
    float4 v = out[i];
    v.x = (v.x - mean) * inv;
    v.y = (v.y - mean) * inv;
    v.z = (v.z - mean) * inv;
    v.w = (v.w - mean) * inv;
    out[i] = v;
}

// ---------------- launch ------------------------------------------------------
extern "C" void kernel_launch(void* const* d_in, const int* in_sizes, int n_in,
                              void* d_out, int out_size) {
    const float* x = (const float*)d_in[0];
    float* out = (float*)d_out;

    init_kernel<<<1, 1024>>>();
    melspec_kernel<<<dim3((NFRAMES + 3) / 4, BATCH), 256>>>(x);
    pcen_kernel<<<BATCH, NMELS>>>(out);
    int total4 = BATCH * NMELS * NFRAMES / 4;
    norm_kernel<<<(total4 + 255) / 256, 256>>>((float4*)out, total4);
}

// round 4
// speedup vs baseline: 3.4218x; 2.3539x over previous
#include <cuda_runtime.h>

#define BATCH   128
#define LSIG    128000
#define NFFT    1024
#define HOP     320
#define NMELS   128
#define NFRAMES 401
#define NFREQ   513
#define MAXW    40
#define PI_D    3.14159265358979323846

// ---------------- device globals (no allocations allowed) -------------------
__device__ float2 g_win2[512];                 // (w[2n], w[2n+1]) interleaved hann
__device__ float2 g_tw[512];                   // W_1024^k = e^{-2*pi*i*k/1024}
__device__ int    g_mlo[NMELS];
__device__ int    g_mlen[NMELS];
__device__ float  g_fbw[MAXW][NMELS];          // transposed: coalesced by m
__device__ float  g_mel[BATCH * NFRAMES * NMELS];
__device__ float  g_stats[BATCH][2];

// ---------------- complex helpers -------------------------------------------
__device__ __forceinline__ float2 cadd(float2 a, float2 b){return make_float2(a.x+b.x, a.y+b.y);}
__device__ __forceinline__ float2 csub(float2 a, float2 b){return make_float2(a.x-b.x, a.y-b.y);}
__device__ __forceinline__ float2 cmul(float2 a, float2 b){return make_float2(a.x*b.x - a.y*b.y, a.x*b.y + a.y*b.x);}

__device__ __forceinline__ float2 twl512(const float2* tws, int m) {
    float2 w = tws[m & 255];
    return (m & 256) ? make_float2(-w.x, -w.y) : w;
}

// in-place 8-point DFT, all registers
__device__ __forceinline__ void dft8(float2 v[8]) {
    const float C = 0.70710678118654752f;
    float2 s0 = cadd(v[0], v[4]), d0 = csub(v[0], v[4]);
    float2 s1 = cadd(v[2], v[6]), d1 = csub(v[2], v[6]);
    float2 s2 = cadd(v[1], v[5]), d2 = csub(v[1], v[5]);
    float2 s3 = cadd(v[3], v[7]), d3 = csub(v[3], v[7]);
    float2 e0 = cadd(s0, s1), e2 = csub(s0, s1);
    float2 nid1 = make_float2(d1.y, -d1.x);
    float2 e1 = cadd(d0, nid1), e3 = csub(d0, nid1);
    float2 o0 = cadd(s2, s3), o2 = csub(s2, s3);
    float2 nid3 = make_float2(d3.y, -d3.x);
    float2 o1 = cadd(d2, nid3), o3 = csub(d2, nid3);
    float2 t1 = make_float2(C*(o1.x + o1.y), C*(o1.y - o1.x));
    float2 t2 = make_float2(o2.y, -o2.x);
    float2 t3 = make_float2(C*(o3.y - o3.x), -C*(o3.x + o3.y));
    v[0] = cadd(e0, o0); v[4] = csub(e0, o0);
    v[1] = cadd(e1, t1); v[5] = csub(e1, t1);
    v[2] = cadd(e2, t2); v[6] = csub(e2, t2);
    v[3] = cadd(e3, t3); v[7] = csub(e3, t3);
}

#define PAD(i) ((i) + ((i) >> 3))   // 512 logical -> 576 physical

// ---------------- init: FULLY PARALLEL (was the hidden serial fp64 hog) -----
// blocks 0..127: filterbank row m (one (m,f) pair per thread)
// blocks 128..135: window + twiddle (64 entries per block)
__global__ void init_kernel() {
    const int bx = blockIdx.x, tid = threadIdx.x;

    if (bx < NMELS) {
        __shared__ double sf[3];
        __shared__ double si01, si12;
        __shared__ int s_lo, s_hi;
        if (tid == 0) { s_lo = 1 << 30; s_hi = -1; }
        if (tid < 3) {
            double mel_max = 2595.0 * log10(1.0 + 16000.0 / 700.0);
            sf[tid] = 700.0 * (pow(10.0, (mel_max * (double)(bx + tid) / 129.0) / 2595.0) - 1.0);
        }
        __syncthreads();
        if (tid == 0) { si01 = 1.0 / (sf[1] - sf[0]); si12 = 1.0 / (sf[2] - sf[1]); }
        __syncthreads();

        double wgt = -1.0;
        if (tid < NFREQ) {
            double freq = (double)tid * (16000.0 / 512.0);
            wgt = fmin((freq - sf[0]) * si01, (sf[2] - freq) * si12);
            if (wgt > 0.0) { atomicMin(&s_lo, tid); atomicMax(&s_hi, tid); }
        }
        __syncthreads();
        int lo = s_lo, hi = s_hi;
        if (tid == 0) {
            if (hi < 0) { g_mlo[bx] = 0; g_mlen[bx] = 0; }
            else {
                int len = hi - lo + 1;
                if (len > MAXW) len = MAXW;
                g_mlo[bx] = lo; g_mlen[bx] = len;
            }
        }
        if (wgt > 0.0) {
            int i = tid - lo;
            if (i >= 0 && i < MAXW) g_fbw[i][bx] = (float)wgt;
        }
    } else {
        int i = (bx - NMELS) * 64 + tid;       // 8 blocks x 64 -> 512
        if (tid < 64 && i < 512) {
            double w0 = 0.5 * (1.0 - cos(2.0 * PI_D * (double)(2 * i)     / (double)NFFT));
            double w1 = 0.5 * (1.0 - cos(2.0 * PI_D * (double)(2 * i + 1) / (double)NFFT));
            g_win2[i] = make_float2((float)w0, (float)w1);
            double s, c;
            sincos(-2.0 * PI_D * (double)i / (double)NFFT, &s, &c);
            g_tw[i] = make_float2((float)c, (float)s);
        }
    }
}

// ---------------- mel spectrogram: ONE WARP PER FRAME ------------------------
// 128 threads = 4 warps = 4 frames per CTA. Each lane holds 2 "virtual
// threads" (vt = lane, lane+32), 8 complex points each. Radix-8 Stockham,
// 3 stages, single per-warp buffer, only __syncwarp between phases:
// no CTA-wide barriers after the twiddle staging -> no cross-frame convoying.
__global__ __launch_bounds__(128) void melspec_kernel(const float* __restrict__ x) {
    __shared__ float2 buf[4][576];
    __shared__ float  swm[4][520];
    __shared__ float2 tws[256];                 // W_512^{0..255}

    const int tid  = threadIdx.x;
    const int w    = tid >> 5;
    const int lane = tid & 31;

    tws[tid]       = g_tw[2 * tid];
    tws[tid + 128] = g_tw[2 * (tid + 128)];
    __syncthreads();                            // only CTA-wide barrier

    int t = blockIdx.x * 4 + w;
    const bool valid = (t < NFRAMES);
    if (!valid) t = NFRAMES - 1;
    const int b = blockIdx.y;

    // load: z[n] = x[2n]w[2n] + i x[2n+1]w[2n+1]; vt holds n = vt + 64j
    const float* __restrict__ xb = x + (long long)b * LSIG;
    const int base = t * HOP - 512;             // even
    float2 v[2][8];
    if (base >= 0 && base + (NFFT - 1) < LSIG) {
        const float2* __restrict__ x2 = (const float2*)(xb + base);
        #pragma unroll
        for (int h = 0; h < 2; h++)
        #pragma unroll
        for (int j = 0; j < 8; j++) {
            int n = lane + 32 * h + 64 * j;
            float2 s  = x2[n];
            float2 wn = g_win2[n];
            v[h][j] = make_float2(s.x * wn.x, s.y * wn.y);
        }
    } else {
        #pragma unroll
        for (int h = 0; h < 2; h++)
        #pragma unroll
        for (int j = 0; j < 8; j++) {
            int n  = lane + 32 * h + 64 * j;
            int p0 = base + 2 * n, p1 = p0 + 1;
            p0 = p0 < 0 ? -p0 : (p0 >= LSIG ? 2 * LSIG - 2 - p0 : p0);
            p1 = p1 < 0 ? -p1 : (p1 >= LSIG ? 2 * LSIG - 2 - p1 : p1);
            float2 wn = g_win2[n];
            v[h][j] = make_float2(xb[p0] * wn.x, xb[p1] * wn.y);
        }
    }

    // ---- stage 0: out[8*vt + k] = DFT8_k * W512^{vt*k}
    #pragma unroll
    for (int h = 0; h < 2; h++) {
        int vt = lane + 32 * h;
        dft8(v[h]);
        #pragma unroll
        for (int k = 1; k < 8; k++) v[h][k] = cmul(v[h][k], twl512(tws, vt * k));
        #pragma unroll
        for (int k = 0; k < 8; k++) buf[w][PAD(8 * vt + k)] = v[h][k];
    }
    __syncwarp();

    // ---- stage 1: out[64p + q + 8k] = DFT8_k * W512^{8pk}, p=vt>>3, q=vt&7
    #pragma unroll
    for (int h = 0; h < 2; h++)
    #pragma unroll
    for (int j = 0; j < 8; j++)
        v[h][j] = buf[w][PAD(lane + 32 * h + 64 * j)];
    __syncwarp();
    #pragma unroll
    for (int h = 0; h < 2; h++) {
        int vt = lane + 32 * h, p = vt >> 3, q = vt & 7;
        dft8(v[h]);
        #pragma unroll
        for (int k = 1; k < 8; k++) v[h][k] = cmul(v[h][k], twl512(tws, 8 * p * k));
        #pragma unroll
        for (int k = 0; k < 8; k++) buf[w][PAD(64 * p + q + 8 * k)] = v[h][k];
    }
    __syncwarp();

    // ---- stage 2: out[vt + 64k] = DFT8_k (no twiddle)
    #pragma unroll
    for (int h = 0; h < 2; h++)
    #pragma unroll
    for (int j = 0; j < 8; j++)
        v[h][j] = buf[w][PAD(lane + 32 * h + 64 * j)];
    __syncwarp();
    #pragma unroll
    for (int h = 0; h < 2; h++) {
        int vt = lane + 32 * h;
        dft8(v[h]);
        #pragma unroll
        for (int k = 0; k < 8; k++) buf[w][PAD(vt + 64 * k)] = v[h][k];
    }
    __syncwarp();

    // ---- unpack rfft magnitudes: X[k] = E[k] + W_1024^k * O[k]
    #pragma unroll
    for (int h = 0; h < 2; h++)
    #pragma unroll
    for (int r = 0; r < 8; r++) {
        int k = lane + 32 * h + 64 * r;
        float2 Zk = buf[w][PAD(k)];
        float2 Zr = buf[w][PAD((512 - k) & 511)];
        float ex = 0.5f * (Zk.x + Zr.x), ey = 0.5f * (Zk.y - Zr.y);
        float ox = 0.5f * (Zk.y + Zr.y), oy = 0.5f * (Zr.x - Zk.x);
        float2 tw = g_tw[k];
        float xr = ex + ox * tw.x - oy * tw.y;
        float xi = ey + ox * tw.y + oy * tw.x;
        swm[w][k] = sqrtf(xr * xr + xi * xi);
    }
    if (lane == 0) {
        float2 Z0 = buf[w][PAD(0)];
        swm[w][512] = fabsf(Z0.x - Z0.y);        // Nyquist
    }
    __syncwarp();

    // ---- mel gather: lane handles mels lane + 32g
    if (valid) {
        float* __restrict__ om = g_mel + ((long long)b * NFRAMES + t) * NMELS;
        #pragma unroll
        for (int g = 0; g < 4; g++) {
            int m   = lane + 32 * g;
            int lo  = g_mlo[m];
            int len = g_mlen[m];
            float acc = 0.0f;
            for (int i = 0; i < len; i++)
                acc += swm[w][lo + i] * g_fbw[i][m];
            om[m] = acc;
        }
    }
}

// ---------------- PCEN IIR + power law + per-batch stats --------------------
__global__ __launch_bounds__(NMELS) void pcen_kernel(float* __restrict__ out) {
    const int b = blockIdx.x;
    const int m = threadIdx.x;

    const float* __restrict__ mel = g_mel + (long long)b * NFRAMES * NMELS;
    float* __restrict__ ob = out + ((long long)b * NMELS + m) * NFRAMES;

    const float s1 = 0.975f, s0 = 0.025f;
    const float sqrt2 = 1.41421356237309515f;

    float M = 0.0f;
    double sum = 0.0, sumsq = 0.0;

    float xnext = mel[m];
    for (int t = 0; t < NFRAMES; t++) {
        float xv = xnext;
        if (t + 1 < NFRAMES) xnext = mel[(t + 1) * NMELS + m];
        M = (t == 0) ? xv : fmaf(s1, M, s0 * xv);
        float smooth = __powf(1e-6f + M, 0.98f);
        float p = sqrtf(xv / smooth + 2.0f) - sqrt2;
        ob[t] = p;
        sum   += (double)p;
        sumsq += (double)p * (double)p;
    }

    __shared__ double ssum[NMELS];
    __shared__ double ssq[NMELS];
    ssum[m] = sum; ssq[m] = sumsq;
    __syncthreads();
    for (int o = NMELS / 2; o > 0; o >>= 1) {
        if (m < o) { ssum[m] += ssum[m + o]; ssq[m] += ssq[m + o]; }
        __syncthreads();
    }
    if (m == 0) {
        const double n = (double)(NMELS * NFRAMES);
        double mean = ssum[0] / n;
        double var  = (ssq[0] - ssum[0] * ssum[0] / n) / (n - 1.0);
        if (var < 0.0) var = 0.0;
        g_stats[b][0] = (float)mean;
        g_stats[b][1] = (float)(1.0 / (sqrt(var) + 1e-6));
    }
}

// ---------------- in-place standardization (vectorized) ---------------------
__global__ void norm_kernel(float4* __restrict__ out, int total4) {
    int i = blockIdx.x * blockDim.x + threadIdx.x;
    if (i >= total4) return;
    int b = (i * 4) / (NMELS * NFRAMES);        // 51328 % 4 == 0: no straddle
    float mean = g_stats[b][0], inv = g_stats[b][1];
    float4 v = out[i];
    v.x = (v.x - mean) * inv;
    v.y = (v.y - mean) * inv;
    v.z = (v.z - mean) * inv;
    v.w = (v.w - mean) * inv;
    out[i] = v;
}

// ---------------- launch ------------------------------------------------------
extern "C" void kernel_launch(void* const* d_in, const int* in_sizes, int n_in,
                              void* d_out, int out_size) {
    const float* x = (const float*)d_in[0];
    float* out = (float*)d_out;

    init_kernel<<<NMELS + 8, 544>>>();
    melspec_kernel<<<dim3((NFRAMES + 3) / 4, BATCH), 128>>>(x);
    pcen_kernel<<<BATCH, NMELS>>>(out);
    int total4 = BATCH * NMELS * NFRAMES / 4;
    norm_kernel<<<(total4 + 255) / 256, 256>>>((float4*)out, total4);
}